// round 12
// baseline (speedup 1.0000x reference)
#include <cuda_runtime.h>

#define NFFT 16384
#define THREADS 512
#define PI_F 3.14159265358979323846f
#define SQRT_HALF 0.70710678118654752440f

// cos/sin(pi*j/8), j=0..7  (= e^{+j*pi/8*j} components; also radix-16 twiddles)
__constant__ float C16[8] = {
    1.0f, 0.92387953251128675613f, 0.70710678118654752440f, 0.38268343236508977173f,
    0.0f,-0.38268343236508977173f,-0.70710678118654752440f,-0.92387953251128675613f };
__constant__ float S16[8] = {
    0.0f, 0.38268343236508977173f, 0.70710678118654752440f, 0.92387953251128675613f,
    1.0f, 0.92387953251128675613f, 0.70710678118654752440f, 0.38268343236508977173f };

struct cplx { float x, y; };

__device__ __forceinline__ cplx padd(cplx a, cplx b) {
    cplx r;
    asm("{\n\t.reg .b64 ra, rb, rr;\n\t"
        "mov.b64 ra, {%2, %3};\n\tmov.b64 rb, {%4, %5};\n\t"
        "add.rn.f32x2 rr, ra, rb;\n\tmov.b64 {%0, %1}, rr;\n\t}"
        : "=f"(r.x), "=f"(r.y) : "f"(a.x), "f"(a.y), "f"(b.x), "f"(b.y));
    return r;
}
__device__ __forceinline__ cplx psub(cplx a, cplx b, unsigned long long neg1) {
    cplx r;
    asm("{\n\t.reg .b64 ra, rb, rr;\n\t"
        "mov.b64 ra, {%2, %3};\n\tmov.b64 rb, {%4, %5};\n\t"
        "fma.rn.f32x2 rr, rb, %6, ra;\n\tmov.b64 {%0, %1}, rr;\n\t}"
        : "=f"(r.x), "=f"(r.y) : "f"(a.x), "f"(a.y), "f"(b.x), "f"(b.y), "l"(neg1));
    return r;
}

// In-place DIF radix-16 inverse FFT (e^{+j}). Natural in, digit-reversed out.
__device__ __forceinline__ void fft16_inv(cplx* r, unsigned long long neg1) {
    #pragma unroll
    for (int half = 8; half >= 1; half >>= 1) {
        #pragma unroll
        for (int base = 0; base < 16; base += 2 * half) {
            #pragma unroll
            for (int j = 0; j < half; j++) {
                cplx a = r[base + j];
                cplx b = r[base + half + j];
                r[base + j] = padd(a, b);
                cplx d = psub(a, b, neg1);
                const int tw = j * (8 / half);
                if (tw == 0)      { r[base+half+j] = d; }
                else if (tw == 4) { r[base+half+j].x = -d.y; r[base+half+j].y = d.x; }
                else {
                    float c = C16[tw], s = S16[tw];
                    r[base+half+j].x = d.x * c - d.y * s;
                    r[base+half+j].y = d.x * s + d.y * c;
                }
            }
        }
    }
}

// Slot layout: 4096 float4 slots; logical position pi -> slot pi ^ ((pi>>8)&15).
// Slot holds two float2 halves (A,B): A at f2[2*sl + ha], B at f2[2*sl + 1-ha],
// ha = bit3 of slot low digit (de-conflicts 16-lane LDS.64 phases).
__device__ __forceinline__ int slotof(int pi) { return pi ^ ((pi >> 8) & 15); }

// Per-group barrier: group A = threads [0,256), barrier 1; group B = [256,512), barrier 2.
__device__ __forceinline__ void group_bar(int t) {
    if (t < 256) { asm volatile("bar.sync 1, 256;" ::: "memory"); }
    else         { asm volatile("bar.sync 2, 256;" ::: "memory"); }
}

__global__ void __launch_bounds__(THREADS, 2)
idxct_kernel(const float* __restrict__ x, float* __restrict__ y)
{
    extern __shared__ float smem[];
    float2* f2  = (float2*)smem;
    float4* f4p = (float4*)smem;

    const int row = blockIdx.x;
    const int t   = threadIdx.x;

    unsigned long long NEG1;
    asm("mov.b64 %0, 0xBF800000BF800000;" : "=l"(NEG1));

    const int REV4[16] = {0,8,4,12,2,10,6,14,1,9,5,13,3,11,7,15};

    // ---- Phase 0: stage x as pairs. Slot v holds (x[2v],x[2v+8192] | x[2v+1],x[2v+8193]).
    {
        const float4* x4 = (const float4*)(x + (size_t)row * NFFT);
        #pragma unroll
        for (int j = 0; j < 8; j++) {
            int v = t + THREADS * j;
            float4 a = x4[v >> 1];
            float4 b = x4[(v >> 1) + 2048];
            int rs = v & 1;
            float xl0 = rs ? a.z : a.x, xl1 = rs ? a.w : a.y;
            float xh0 = rs ? b.z : b.x, xh1 = rs ? b.w : b.y;
            int sl = slotof(v);
            int ha = (sl >> 3) & 1;
            f4p[sl] = ha ? make_float4(xl1, xh1, xl0, xh0)
                         : make_float4(xl0, xh0, xl1, xh1);
        }
    }
    __syncthreads();

    // ---- Phase 1a: spectrum build, split by half.
    // Group A (t<256): even m = 2u, pairs (u, 4096-u), u = n1*256+t, n1=0..7.
    // Group B (t>=256): odd m = 2u+1, pairs (u, 4095-u), u = n1*256+(t-256).
    {
        const float cD = 0.99879545620517239271f;   // cos(pi/64)  (u step = 256 -> m step 512)
        const float sD = 0.04906767432741801426f;   // sin(pi/64)
        if (t < 256) {
            float cb, sb;
            __sincosf((float)(2 * t) * (PI_F / 32768.0f), &sb, &cb);
            #pragma unroll
            for (int n1 = 0; n1 < 8; n1++) {
                int u = n1 * 256 + t;
                if (u == 0) {
                    float2 P = f2[0];
                    float ux = 2.0f * P.x + 2.0f * SQRT_HALF * P.y;
                    float vx = 2.0f * P.x - 2.0f * SQRT_HALF * P.y;
                    f2[0] = make_float2(0.5f * ux, 0.5f * vx);
                    {   // q_2048 (m=4096, self-partner)
                        const float c8 = 0.92387953251128675613f;
                        const float s8 = 0.38268343236508977173f;
                        int sl2 = slotof(2048);
                        int ha2 = (sl2 >> 3) & 1;
                        float2 P2 = f2[2 * sl2 + ha2];
                        float e2x = (c8 - s8) * SQRT_HALF, e2y = (c8 + s8) * SQRT_HALF;
                        float t2x = 2.0f * e2x * e2y, t2y = 2.0f * c8 * s8;
                        float tx = t2x * t2x - t2y * t2y, ty = 2.0f * t2x * t2y;
                        float s1x = P2.x * c8 + P2.y * s8, s1y = P2.x * s8 - P2.y * c8;
                        float s2x = P2.y * e2x + P2.x * e2y, s2y = P2.y * e2y - P2.x * e2x;
                        float ux2 = s1x + s2x, uy2 = s1y + s2y;
                        float vx2 = s1x - s2x, vy2 = s1y - s2y;
                        float gx = tx * vy2 + ty * vx2, gy = tx * vx2 - ty * vy2;
                        f2[2 * sl2 + ha2] = make_float2(0.5f * (ux2 - gx), 0.5f * (uy2 + gy));
                    }
                } else {
                    int up = 4096 - u;
                    int slu = slotof(u),  hau = (slu >> 3) & 1;
                    int slp = slotof(up), hap = (slp >> 3) & 1;
                    float2 P = f2[2 * slu + hau];
                    float2 Q = f2[2 * slp + hap];
                    float e2x = (cb - sb) * SQRT_HALF, e2y = (cb + sb) * SQRT_HALF;
                    float t2x = 2.0f * e2x * e2y, t2y = 2.0f * cb * sb;
                    float tx = t2x * t2x - t2y * t2y, ty = 2.0f * t2x * t2y;
                    float s1x = P.x * cb + Q.y * sb,  s1y = P.x * sb - Q.y * cb;
                    float s2x = P.y * e2x + Q.x * e2y, s2y = P.y * e2y - Q.x * e2x;
                    float ux = s1x + s2x, uy = s1y + s2y;
                    float vx = s1x - s2x, vy = s1y - s2y;
                    float gx = tx * vy + ty * vx, gy = tx * vx - ty * vy;
                    f2[2 * slu + hau] = make_float2(0.5f * (ux - gx), 0.5f * (uy + gy));
                    f2[2 * slp + hap] = make_float2(0.5f * (ux + gx), 0.5f * (gy - uy));
                }
                float ncb = cb * cD - sb * sD;
                sb = sb * cD + cb * sD;
                cb = ncb;
            }
        } else {
            const int tb = t - 256;
            float cb, sb;
            __sincosf((float)(2 * tb + 1) * (PI_F / 32768.0f), &sb, &cb);
            #pragma unroll
            for (int n1 = 0; n1 < 8; n1++) {
                int u = n1 * 256 + tb;
                int up = 4095 - u;
                int slu = slotof(u),  hau = (slu >> 3) & 1;
                int slp = slotof(up), hap = (slp >> 3) & 1;
                float2 P = f2[2 * slu + (hau ^ 1)];
                float2 Q = f2[2 * slp + (hap ^ 1)];
                float e2x = (cb - sb) * SQRT_HALF, e2y = (cb + sb) * SQRT_HALF;
                float t2x = 2.0f * e2x * e2y, t2y = 2.0f * cb * sb;
                float tx = t2x * t2x - t2y * t2y, ty = 2.0f * t2x * t2y;
                float s1x = P.x * cb + Q.y * sb,  s1y = P.x * sb - Q.y * cb;
                float s2x = P.y * e2x + Q.x * e2y, s2y = P.y * e2y - Q.x * e2x;
                float ux = s1x + s2x, uy = s1y + s2y;
                float vx = s1x - s2x, vy = s1y - s2y;
                float gx = tx * vy + ty * vx, gy = tx * vx - ty * vy;
                f2[2 * slu + (hau ^ 1)] = make_float2(0.5f * (ux - gx), 0.5f * (uy + gy));
                f2[2 * slp + (hap ^ 1)] = make_float2(0.5f * (ux + gx), 0.5f * (gy - uy));
                float ncb = cb * cD - sb * sD;
                sb = sb * cD + cb * sD;
                cb = ncb;
            }
        }
    }
    group_bar(t);   // A-half producers == A-half consumers (and same for B)

    // ---- Pass 1: radix-16 over n1, twiddle W_4096^{+tp*k1}. One chunk per thread.
    {
        const int h  = t >> 8;
        const int tp = t & 255;
        cplx r[16];
        #pragma unroll
        for (int n1 = 0; n1 < 16; n1++) {
            int sl = (n1 * 256 + tp) ^ n1;
            float2 v = f2[2 * sl + ((((sl >> 3) & 1)) ^ h)];
            r[n1].x = v.x; r[n1].y = v.y;
        }
        fft16_inv(r, NEG1);
        // Quad-decomposed twiddles: base advances by w^4; within quad multiply by w.
        float w1c, w1s;
        __sincosf((float)tp * (2.0f * PI_F / 4096.0f), &w1s, &w1c);
        float w2c = w1c * w1c - w1s * w1s, w2s = 2.0f * w1c * w1s;
        float w4c = w2c * w2c - w2s * w2s, w4s = 2.0f * w2c * w2s;
        float bc = 1.0f, bs = 0.0f;
        #pragma unroll
        for (int g = 0; g < 4; g++) {
            float twc = bc, tws = bs;
            #pragma unroll
            for (int l = 0; l < 4; l++) {
                const int k1 = 4 * g + l;
                const int i = REV4[k1];
                float vx = r[i].x * twc - r[i].y * tws;
                float vy = r[i].x * tws + r[i].y * twc;
                int sl = (k1 * 256 + tp) ^ k1;
                f2[2 * sl + ((((sl >> 3) & 1)) ^ h)] = make_float2(vx, vy);
                float ntc = twc * w1c - tws * w1s;      // within-quad: depth <=3
                tws = tws * w1c + twc * w1s;
                twc = ntc;
            }
            float nbc = bc * w4c - bs * w4s;            // base chain: depth 4
            bs = bs * w4c + bc * w4s;
            bc = nbc;
        }
    }
    group_bar(t);

    // ---- Pass 2: radix-16 over middle digit, twiddle W_256^{+b*k2}.
    {
        const int h  = t >> 8;
        const int th = t & 255;
        const int k1 = th & 15;
        const int b  = th >> 4;
        const int slbase = (k1 << 8) + (b ^ k1);
        const int off = ((((b ^ k1) >> 3) & 1) ^ h);
        cplx r[16];
        #pragma unroll
        for (int a = 0; a < 16; a++) {
            float2 v = f2[2 * (slbase + a * 16) + off];
            r[a].x = v.x; r[a].y = v.y;
        }
        fft16_inv(r, NEG1);
        float w1c, w1s;
        __sincosf((float)b * (PI_F / 128.0f), &w1s, &w1c);
        float w2c = w1c * w1c - w1s * w1s, w2s = 2.0f * w1c * w1s;
        float w4c = w2c * w2c - w2s * w2s, w4s = 2.0f * w2c * w2s;
        float bc = 1.0f, bs = 0.0f;
        #pragma unroll
        for (int g = 0; g < 4; g++) {
            float twc = bc, tws = bs;
            #pragma unroll
            for (int l = 0; l < 4; l++) {
                const int k2 = 4 * g + l;
                const int i = REV4[k2];
                float vx = r[i].x * twc - r[i].y * tws;
                float vy = r[i].x * tws + r[i].y * twc;
                f2[2 * (slbase + k2 * 16) + off] = make_float2(vx, vy);
                float ntc = twc * w1c - tws * w1s;
                tws = tws * w1c + twc * w1s;
                twc = ntc;
            }
            float nbc = bc * w4c - bs * w4s;
            bs = bs * w4c + bc * w4s;
            bc = nbc;
        }
    }
    group_bar(t);

    // ---- Pass 3: radix-16 over low digit, no twiddle. One half per thread.
    {
        const int h  = t >> 8;
        const int th = t & 255;
        const int k1 = th & 15;
        const int c  = th >> 4;
        const int base0 = (k1 << 8) + (c << 4);
        cplx r[16];
        #pragma unroll
        for (int d = 0; d < 16; d++) {
            int lo = d ^ k1;
            float2 v = f2[2 * (base0 + lo) + (((lo >> 3) & 1) ^ h)];
            r[d].x = v.x; r[d].y = v.y;
        }
        fft16_inv(r, NEG1);
        #pragma unroll
        for (int i = 0; i < 16; i++) {
            int lo = REV4[i] ^ k1;
            f2[2 * (base0 + lo) + (((lo >> 3) & 1) ^ h)] = make_float2(r[i].x, r[i].y);
        }
    }
    __syncthreads();   // gather reads both halves

    // ---- Gather: radix-2 combine + de-permute, contiguous float4 stores.
    // z_q        = A_q + w^q B_q,  w = e^{+j*2*pi/8192}
    // z_{8191-q} = M + conj-rotated N (folded via w^{q+1})
    // y[4q]=Re z_q, y[4q+1]=Im z_{8191-q}, y[4q+2]=Im z_q, y[4q+3]=Re z_{8191-q}
    {
        float4* y4 = (float4*)(y + (size_t)row * NFFT);
        const float c1 = 0.99999970586288222663f;      // cos(2*pi/8192)
        const float s1 = 7.66990318742704526939e-4f;   // sin(2*pi/8192)
        float wtc, wts;
        __sincosf((float)t * (2.0f * PI_F / 8192.0f), &wts, &wtc);
        const int d0 = t & 15, d1 = (t >> 4) & 15;
        const int baseA = (d0 << 8) + (d1 << 4);
        const int baseM = ((15 - d0) << 8) + ((15 - d1) << 4);
        #pragma unroll
        for (int jj = 0; jj < 8; jj++) {
            int qo = t + THREADS * jj;                 // [0, 4096)
            int d2 = qo >> 8;
            int loA = d2 ^ d0;
            int loM = (15 - d2) ^ (15 - d0);
            float2 A  = f2[2 * (baseA + loA) + (((loA >> 3) & 1))];
            float2 B  = f2[2 * (baseA + loA) + (((loA >> 3) & 1) ^ 1)];
            float2 M  = f2[2 * (baseM + loM) + (((loM >> 3) & 1))];
            float2 Nw = f2[2 * (baseM + loM) + (((loM >> 3) & 1) ^ 1)];
            // w^qo = w_t * e^{j*pi/8*jj}: constant rotation, no serial chain
            float wc = wtc * C16[jj] - wts * S16[jj];
            float ws = wtc * S16[jj] + wts * C16[jj];
            float ox = wc * c1 - ws * s1;              // w^{qo+1}
            float oy = wc * s1 + ws * c1;
            cplx wB, oN, Ac, Mc;
            wB.x = wc * B.x - ws * B.y;
            wB.y = wc * B.y + ws * B.x;
            oN.x = ox * Nw.x + oy * Nw.y;
            oN.y = ox * Nw.y - oy * Nw.x;
            Ac.x = A.x; Ac.y = A.y;
            Mc.x = M.x; Mc.y = M.y;
            cplx z1 = padd(Ac, wB);
            cplx z2 = padd(Mc, oN);
            y4[qo] = make_float4(z1.x, z2.y, z1.y, z2.x);
        }
    }
}

extern "C" void kernel_launch(void* const* d_in, const int* in_sizes, int n_in,
                              void* d_out, int out_size)
{
    const float* x = (const float*)d_in[0];
    float*       y = (float*)d_out;

    const int rows = in_sizes[0] / NFFT;
    const int smem_bytes = NFFT * (int)sizeof(float);   // 64 KB

    cudaFuncSetAttribute(idxct_kernel,
                         cudaFuncAttributeMaxDynamicSharedMemorySize, smem_bytes);

    idxct_kernel<<<rows, THREADS, smem_bytes>>>(x, y);
}

// round 13
// speedup vs baseline: 1.1057x; 1.1057x over previous
#include <cuda_runtime.h>

#define NFFT 16384
#define THREADS 512
#define PI_F 3.14159265358979323846f
#define SQRT_HALF 0.70710678118654752440f

// cos/sin(pi*j/8), j=0..7 (radix-16 twiddles; also e^{j*pi*j/8} steps)
__constant__ float C16[8] = {
    1.0f, 0.92387953251128675613f, 0.70710678118654752440f, 0.38268343236508977173f,
    0.0f,-0.38268343236508977173f,-0.70710678118654752440f,-0.92387953251128675613f };
__constant__ float S16[8] = {
    0.0f, 0.38268343236508977173f, 0.70710678118654752440f, 0.92387953251128675613f,
    1.0f, 0.92387953251128675613f, 0.70710678118654752440f, 0.38268343236508977173f };

struct cplx { float x, y; };

__device__ __forceinline__ cplx padd(cplx a, cplx b) {
    cplx r;
    asm("{\n\t.reg .b64 ra, rb, rr;\n\t"
        "mov.b64 ra, {%2, %3};\n\tmov.b64 rb, {%4, %5};\n\t"
        "add.rn.f32x2 rr, ra, rb;\n\tmov.b64 {%0, %1}, rr;\n\t}"
        : "=f"(r.x), "=f"(r.y) : "f"(a.x), "f"(a.y), "f"(b.x), "f"(b.y));
    return r;
}
__device__ __forceinline__ cplx psub(cplx a, cplx b, unsigned long long neg1) {
    cplx r;
    asm("{\n\t.reg .b64 ra, rb, rr;\n\t"
        "mov.b64 ra, {%2, %3};\n\tmov.b64 rb, {%4, %5};\n\t"
        "fma.rn.f32x2 rr, rb, %6, ra;\n\tmov.b64 {%0, %1}, rr;\n\t}"
        : "=f"(r.x), "=f"(r.y) : "f"(a.x), "f"(a.y), "f"(b.x), "f"(b.y), "l"(neg1));
    return r;
}

// In-place DIF radix-16 inverse FFT (e^{+j}). Natural in, digit-reversed out.
__device__ __forceinline__ void fft16_inv(cplx* r, unsigned long long neg1) {
    #pragma unroll
    for (int half = 8; half >= 1; half >>= 1) {
        #pragma unroll
        for (int base = 0; base < 16; base += 2 * half) {
            #pragma unroll
            for (int j = 0; j < half; j++) {
                cplx a = r[base + j];
                cplx b = r[base + half + j];
                r[base + j] = padd(a, b);
                cplx d = psub(a, b, neg1);
                const int tw = j * (8 / half);
                if (tw == 0)      { r[base+half+j] = d; }
                else if (tw == 4) { r[base+half+j].x = -d.y; r[base+half+j].y = d.x; }
                else {
                    float c = C16[tw], s = S16[tw];
                    r[base+half+j].x = d.x * c - d.y * s;
                    r[base+half+j].y = d.x * s + d.y * c;
                }
            }
        }
    }
}

// Slot layout: 4096 float4 slots; logical position pi -> slot pi ^ ((pi>>8)&15).
// Slot holds two float2 halves (A,B): A at f2[2*sl + ha], B at f2[2*sl + 1-ha],
// ha = bit3 of slot low digit (de-conflicts 16-lane LDS.64 phases).
__device__ __forceinline__ int slotof(int pi) { return pi ^ ((pi >> 8) & 15); }

__global__ void __launch_bounds__(THREADS, 2)
idxct_kernel(const float* __restrict__ x, float* __restrict__ y)
{
    extern __shared__ float smem[];
    float2* f2  = (float2*)smem;
    float4* f4p = (float4*)smem;

    const int row = blockIdx.x;
    const int t   = threadIdx.x;

    unsigned long long NEG1;
    asm("mov.b64 %0, 0xBF800000BF800000;" : "=l"(NEG1));

    const int REV4[16] = {0,8,4,12,2,10,6,14,1,9,5,13,3,11,7,15};

    // ---- Phase 1a: spectrum build straight from gmem (no staging pass).
    // Each thread handles BOTH halves for u = n1*512+t, n1=0..3 (u in [0,2048)):
    //   A: m=2u,   partner 4096-u;  B: m=2u+1, partner 4095-u.
    // s_m = conj(expk_m)*(x_m - j x_{N-m}); q = 0.5[(s_m+s_{m+H}) + j*tau*(s_m-s_{m+H})]
    // Conjugate-pair: q_partner = 0.5*conj(u_vec - g).
    {
        const float2* x2 = (const float2*)(x + (size_t)row * NFFT);
        const float cD = 0.99518472667219688624f;   // cos(pi/32)  (u step = 512)
        const float sD = 0.09801714032956060199f;   // sin(pi/32)
        float cbA, sbA, cbB, sbB;
        __sincosf((float)(2 * t)     * (PI_F / 32768.0f), &sbA, &cbA);
        __sincosf((float)(2 * t + 1) * (PI_F / 32768.0f), &sbB, &cbB);
        #pragma unroll
        for (int n1 = 0; n1 < 4; n1++) {
            int u  = n1 * 512 + t;
            int um = (u == 0) ? 1 : u;              // clamp for OOB-safe loads
            float2 xa  = x2[u];                     // (x[2u],      x[2u+1])
            float2 xc  = x2[4096 + u];              // (x[2u+8192], x[2u+8193])
            float2 xd  = x2[4095 - u];              // (x[8190-2u], x[8191-2u])
            float2 xd2 = x2[4096 - um];             // (x[8192-2u], ...)
            float2 xf  = x2[8191 - u];              // (x[16382-2u], x[16383-2u])
            float2 xf2 = x2[8192 - um];             // (x[16384-2u], ...)

            // ---- B task (always regular) ----
            cplx qBu, qBp;
            {
                float e2x = (cbB - sbB) * SQRT_HALF, e2y = (cbB + sbB) * SQRT_HALF;
                float t2x = 2.0f * e2x * e2y, t2y = 2.0f * cbB * sbB;
                float tx = t2x * t2x - t2y * t2y, ty = 2.0f * t2x * t2y;
                float s1x = xa.y * cbB + xf.y * sbB,  s1y = xa.y * sbB - xf.y * cbB;
                float s2x = xc.y * e2x + xd.y * e2y,  s2y = xc.y * e2y - xd.y * e2x;
                float ux = s1x + s2x, uy = s1y + s2y;
                float vx = s1x - s2x, vy = s1y - s2y;
                float gx = tx * vy + ty * vx, gy = tx * vx - ty * vy;
                qBu.x = 0.5f * (ux - gx); qBu.y = 0.5f * (uy + gy);
                qBp.x = 0.5f * (ux + gx); qBp.y = 0.5f * (gy - uy);
            }

            // ---- A task ----
            cplx qAu;
            if (u != 0) {
                float e2x = (cbA - sbA) * SQRT_HALF, e2y = (cbA + sbA) * SQRT_HALF;
                float t2x = 2.0f * e2x * e2y, t2y = 2.0f * cbA * sbA;
                float tx = t2x * t2x - t2y * t2y, ty = 2.0f * t2x * t2y;
                float s1x = xa.x * cbA + xf2.x * sbA, s1y = xa.x * sbA - xf2.x * cbA;
                float s2x = xc.x * e2x + xd2.x * e2y, s2y = xc.x * e2y - xd2.x * e2x;
                float ux = s1x + s2x, uy = s1y + s2y;
                float vx = s1x - s2x, vy = s1y - s2y;
                float gx = tx * vy + ty * vx, gy = tx * vx - ty * vy;
                qAu.x = 0.5f * (ux - gx); qAu.y = 0.5f * (uy + gy);
                int sp = slotof(4096 - u), hap = (sp >> 3) & 1;
                f2[2 * sp + hap] = make_float2(0.5f * (ux + gx), 0.5f * (gy - uy));
            } else {
                // q_0 from (x0, x8192):
                float x0 = xa.x, x8192 = xc.x;
                float ux = 2.0f * x0 + 2.0f * SQRT_HALF * x8192;
                float vx = 2.0f * x0 - 2.0f * SQRT_HALF * x8192;
                qAu.x = 0.5f * ux; qAu.y = 0.5f * vx;
                // q_2048 (m=4096, self-partner) from (x4096, x12288):
                const float c8 = 0.92387953251128675613f;
                const float s8 = 0.38268343236508977173f;
                float p2x = x2[2048].x, p2y = x2[6144].x;
                float e2x = (c8 - s8) * SQRT_HALF, e2y = (c8 + s8) * SQRT_HALF;
                float t2x = 2.0f * e2x * e2y, t2y = 2.0f * c8 * s8;
                float tx = t2x * t2x - t2y * t2y, ty = 2.0f * t2x * t2y;
                float s1x = p2x * c8 + p2y * s8, s1y = p2x * s8 - p2y * c8;
                float s2x = p2y * e2x + p2x * e2y, s2y = p2y * e2y - p2x * e2x;
                float ux2 = s1x + s2x, uy2 = s1y + s2y;
                float vx2 = s1x - s2x, vy2 = s1y - s2y;
                float gx = tx * vy2 + ty * vx2, gy = tx * vx2 - ty * vy2;
                int sl2 = slotof(2048), ha2 = (sl2 >> 3) & 1;
                f2[2 * sl2 + ha2] = make_float2(0.5f * (ux2 - gx), 0.5f * (uy2 + gy));
            }

            // Combined write of slot u: both halves in one STS.128.
            int sl = slotof(u), ha = (sl >> 3) & 1;
            f4p[sl] = ha ? make_float4(qBu.x, qBu.y, qAu.x, qAu.y)
                         : make_float4(qAu.x, qAu.y, qBu.x, qBu.y);
            // B partner:
            int sq = slotof(4095 - u), haq = (sq >> 3) & 1;
            f2[2 * sq + (haq ^ 1)] = make_float2(qBp.x, qBp.y);

            // advance both trig chains by e^{j*pi/32}
            float n1c = cbA * cD - sbA * sD; sbA = sbA * cD + cbA * sD; cbA = n1c;
            float n2c = cbB * cD - sbB * sD; sbB = sbB * cD + cbB * sD; cbB = n2c;
        }
    }
    __syncthreads();

    // ---- Pass 1: radix-16 over n1, twiddle W_4096^{+tp*k1}. One chunk per thread.
    {
        const int h  = t >> 8;
        const int tp = t & 255;
        float w1c, w1s;
        __sincosf((float)tp * (2.0f * PI_F / 4096.0f), &w1s, &w1c);
        cplx r[16];
        #pragma unroll
        for (int n1 = 0; n1 < 16; n1++) {
            int sl = (n1 * 256 + tp) ^ n1;
            float2 v = f2[2 * sl + ((((sl >> 3) & 1)) ^ h)];
            r[n1].x = v.x; r[n1].y = v.y;
        }
        fft16_inv(r, NEG1);
        float wc = 1.0f, ws = 0.0f;
        #pragma unroll
        for (int k1 = 0; k1 < 16; k1++) {
            const int i = REV4[k1];
            float vx = r[i].x * wc - r[i].y * ws;
            float vy = r[i].x * ws + r[i].y * wc;
            int sl = (k1 * 256 + tp) ^ k1;
            f2[2 * sl + ((((sl >> 3) & 1)) ^ h)] = make_float2(vx, vy);
            float nwc = wc * w1c - ws * w1s;
            ws = ws * w1c + wc * w1s;
            wc = nwc;
        }
    }
    __syncthreads();

    // ---- Pass 2: radix-16 over middle digit, twiddle W_256^{+b*k2}.
    {
        const int h  = t >> 8;
        const int th = t & 255;
        const int k1 = th & 15;
        const int b  = th >> 4;
        float w2c, w2s;
        __sincosf((float)b * (PI_F / 128.0f), &w2s, &w2c);
        const int slbase = (k1 << 8) + (b ^ k1);
        const int off = ((((b ^ k1) >> 3) & 1) ^ h);
        cplx r[16];
        #pragma unroll
        for (int a = 0; a < 16; a++) {
            float2 v = f2[2 * (slbase + a * 16) + off];
            r[a].x = v.x; r[a].y = v.y;
        }
        fft16_inv(r, NEG1);
        float wc = 1.0f, ws = 0.0f;
        #pragma unroll
        for (int k2 = 0; k2 < 16; k2++) {
            const int i = REV4[k2];
            float vx = r[i].x * wc - r[i].y * ws;
            float vy = r[i].x * ws + r[i].y * wc;
            f2[2 * (slbase + k2 * 16) + off] = make_float2(vx, vy);
            float nwc = wc * w2c - ws * w2s;
            ws = ws * w2c + wc * w2s;
            wc = nwc;
        }
    }
    __syncthreads();

    // ---- Pass 3: radix-16 over low digit, no twiddle. One half per thread.
    {
        const int h  = t >> 8;
        const int th = t & 255;
        const int k1 = th & 15;
        const int c  = th >> 4;
        const int base0 = (k1 << 8) + (c << 4);
        cplx r[16];
        #pragma unroll
        for (int d = 0; d < 16; d++) {
            int lo = d ^ k1;
            float2 v = f2[2 * (base0 + lo) + (((lo >> 3) & 1) ^ h)];
            r[d].x = v.x; r[d].y = v.y;
        }
        fft16_inv(r, NEG1);
        #pragma unroll
        for (int i = 0; i < 16; i++) {
            int lo = REV4[i] ^ k1;
            f2[2 * (base0 + lo) + (((lo >> 3) & 1) ^ h)] = make_float2(r[i].x, r[i].y);
        }
    }
    __syncthreads();

    // ---- Gather (pair-dedup): each thread emits outputs qo AND 4095-qo.
    // z_qo       = A + w^qo B           z_{4096+qo} = A - w^qo B
    // z_{8191-qo}= M + conj(w^{qo+1}) N z_{4095-qo} = M - conj(w^{qo+1}) N
    // y4[p] = (Re z_p, Im z_{8191-p}, Im z_p, Re z_{8191-p})
    {
        float4* y4 = (float4*)(y + (size_t)row * NFFT);
        const float c1 = 0.99999970586288222663f;      // cos(2*pi/8192)
        const float s1 = 7.66990318742704526939e-4f;   // sin(2*pi/8192)
        const float cS = 0.92387953251128675613f;      // cos(pi/8)   (qo step 512)
        const float sS = 0.38268343236508977173f;      // sin(pi/8)
        float wc, ws;
        __sincosf((float)t * (2.0f * PI_F / 8192.0f), &ws, &wc);
        const int d0 = t & 15, d1 = (t >> 4) & 15;
        const int baseA = (d0 << 8) + (d1 << 4);
        const int baseM = ((15 - d0) << 8) + ((15 - d1) << 4);
        #pragma unroll
        for (int jj = 0; jj < 4; jj++) {
            int qo = t + THREADS * jj;                 // [0, 2048)
            int d2 = (t >> 8) + 2 * jj;
            int loA = d2 ^ d0;
            int loM = (15 - d2) ^ (15 - d0);
            float4 F = f4p[baseA + loA];               // both halves of slot qo
            float4 G = f4p[baseM + loM];               // both halves of slot 4095-qo
            int haA = (loA >> 3) & 1;
            int haM = (loM >> 3) & 1;
            cplx A, B, M, Nw;
            A.x  = haA ? F.z : F.x;  A.y  = haA ? F.w : F.y;
            B.x  = haA ? F.x : F.z;  B.y  = haA ? F.y : F.w;
            M.x  = haM ? G.z : G.x;  M.y  = haM ? G.w : G.y;
            Nw.x = haM ? G.x : G.z;  Nw.y = haM ? G.y : G.w;
            float ox = wc * c1 - ws * s1;              // w^{qo+1}
            float oy = wc * s1 + ws * c1;
            cplx wB, oN;
            wB.x = wc * B.x - ws * B.y;
            wB.y = wc * B.y + ws * B.x;
            oN.x = ox * Nw.x + oy * Nw.y;              // conj(w^{qo+1}) * N
            oN.y = ox * Nw.y - oy * Nw.x;
            cplx z1 = padd(A, wB);                     // z_qo
            cplx z3 = psub(A, wB, NEG1);               // z_{4096+qo}
            cplx z2 = padd(M, oN);                     // z_{8191-qo}
            cplx z4 = psub(M, oN, NEG1);               // z_{4095-qo}
            y4[qo]        = make_float4(z1.x, z2.y, z1.y, z2.x);
            y4[4095 - qo] = make_float4(z4.x, z3.y, z4.y, z3.x);
            float nwc = wc * cS - ws * sS;             // w *= e^{j*pi/8}
            ws = ws * cS + wc * sS;
            wc = nwc;
        }
    }
}

extern "C" void kernel_launch(void* const* d_in, const int* in_sizes, int n_in,
                              void* d_out, int out_size)
{
    const float* x = (const float*)d_in[0];
    float*       y = (float*)d_out;

    const int rows = in_sizes[0] / NFFT;
    const int smem_bytes = NFFT * (int)sizeof(float);   // 64 KB

    cudaFuncSetAttribute(idxct_kernel,
                         cudaFuncAttributeMaxDynamicSharedMemorySize, smem_bytes);

    idxct_kernel<<<rows, THREADS, smem_bytes>>>(x, y);
}

// round 14
// speedup vs baseline: 1.1695x; 1.0577x over previous
#include <cuda_runtime.h>

#define NFFT 16384
#define THREADS 512
#define PI_F 3.14159265358979323846f
#define SQRT_HALF 0.70710678118654752440f
#define SKEWN 4112   // 16 * 257 slots per plane

// cos/sin(pi*j/8), j=0..7 (radix-16 twiddles; also e^{j*pi*j/8} steps)
__constant__ float C16[8] = {
    1.0f, 0.92387953251128675613f, 0.70710678118654752440f, 0.38268343236508977173f,
    0.0f,-0.38268343236508977173f,-0.70710678118654752440f,-0.92387953251128675613f };
__constant__ float S16[8] = {
    0.0f, 0.38268343236508977173f, 0.70710678118654752440f, 0.92387953251128675613f,
    1.0f, 0.92387953251128675613f, 0.70710678118654752440f, 0.38268343236508977173f };

struct cplx { float x, y; };

__device__ __forceinline__ cplx padd(cplx a, cplx b) {
    cplx r;
    asm("{\n\t.reg .b64 ra, rb, rr;\n\t"
        "mov.b64 ra, {%2, %3};\n\tmov.b64 rb, {%4, %5};\n\t"
        "add.rn.f32x2 rr, ra, rb;\n\tmov.b64 {%0, %1}, rr;\n\t}"
        : "=f"(r.x), "=f"(r.y) : "f"(a.x), "f"(a.y), "f"(b.x), "f"(b.y));
    return r;
}
__device__ __forceinline__ cplx psub(cplx a, cplx b, unsigned long long neg1) {
    cplx r;
    asm("{\n\t.reg .b64 ra, rb, rr;\n\t"
        "mov.b64 ra, {%2, %3};\n\tmov.b64 rb, {%4, %5};\n\t"
        "fma.rn.f32x2 rr, rb, %6, ra;\n\tmov.b64 {%0, %1}, rr;\n\t}"
        : "=f"(r.x), "=f"(r.y) : "f"(a.x), "f"(a.y), "f"(b.x), "f"(b.y), "l"(neg1));
    return r;
}

// In-place DIF radix-16 inverse FFT (e^{+j}). Natural in, digit-reversed out.
__device__ __forceinline__ void fft16_inv(cplx* r, unsigned long long neg1) {
    #pragma unroll
    for (int half = 8; half >= 1; half >>= 1) {
        #pragma unroll
        for (int base = 0; base < 16; base += 2 * half) {
            #pragma unroll
            for (int j = 0; j < half; j++) {
                cplx a = r[base + j];
                cplx b = r[base + half + j];
                r[base + j] = padd(a, b);
                cplx d = psub(a, b, neg1);
                const int tw = j * (8 / half);
                if (tw == 0)      { r[base+half+j] = d; }
                else if (tw == 4) { r[base+half+j].x = -d.y; r[base+half+j].y = d.x; }
                else {
                    float c = C16[tw], s = S16[tw];
                    r[base+half+j].x = d.x * c - d.y * s;
                    r[base+half+j].y = d.x * s + d.y * c;
                }
            }
        }
    }
}

// Skewed index: logical position p (0..4095) -> plane index p + (p>>8).
// Injective into [0, 4112); stride-257 per hi-digit makes every access
// pattern (varying hi OR varying low) bank-conflict-free on a float2 plane.
__device__ __forceinline__ int skidx(int p) { return p + (p >> 8); }

__global__ void __launch_bounds__(THREADS, 2)
idxct_kernel(const float* __restrict__ x, float* __restrict__ y)
{
    extern __shared__ float smem[];
    float2* zA = (float2*)smem;      // A-half plane (even spectrum FFT)
    float2* zB = zA + SKEWN;         // B-half plane (odd spectrum FFT)

    const int row = blockIdx.x;
    const int t   = threadIdx.x;

    unsigned long long NEG1;
    asm("mov.b64 %0, 0xBF800000BF800000;" : "=l"(NEG1));

    const int REV4[16] = {0,8,4,12,2,10,6,14,1,9,5,13,3,11,7,15};

    // ---- Phase 1a: spectrum build straight from gmem.
    // Thread handles u = n1*512+t, n1=0..3: A task m=2u (partner 4096-u),
    // B task m=2u+1 (partner 4095-u). Conjugate-pair trick as R13.
    {
        const float2* x2 = (const float2*)(x + (size_t)row * NFFT);
        const float cD = 0.99518472667219688624f;   // cos(pi/32)
        const float sD = 0.09801714032956060199f;   // sin(pi/32)
        float cbA, sbA, cbB, sbB;
        __sincosf((float)(2 * t)     * (PI_F / 32768.0f), &sbA, &cbA);
        __sincosf((float)(2 * t + 1) * (PI_F / 32768.0f), &sbB, &cbB);
        const int tb = t + (t >> 8);                // skidx of own position
        #pragma unroll
        for (int n1 = 0; n1 < 4; n1++) {
            int u  = n1 * 512 + t;
            int um = (u == 0) ? 1 : u;
            float2 xa  = x2[u];
            float2 xc  = x2[4096 + u];
            float2 xd  = x2[4095 - u];
            float2 xd2 = x2[4096 - um];
            float2 xf  = x2[8191 - u];
            float2 xf2 = x2[8192 - um];

            // ---- B task (always regular) ----
            cplx qBu, qBp;
            {
                float e2x = (cbB - sbB) * SQRT_HALF, e2y = (cbB + sbB) * SQRT_HALF;
                float t2x = 2.0f * e2x * e2y, t2y = 2.0f * cbB * sbB;
                float tx = t2x * t2x - t2y * t2y, ty = 2.0f * t2x * t2y;
                float s1x = xa.y * cbB + xf.y * sbB,  s1y = xa.y * sbB - xf.y * cbB;
                float s2x = xc.y * e2x + xd.y * e2y,  s2y = xc.y * e2y - xd.y * e2x;
                float ux = s1x + s2x, uy = s1y + s2y;
                float vx = s1x - s2x, vy = s1y - s2y;
                float gx = tx * vy + ty * vx, gy = tx * vx - ty * vy;
                qBu.x = 0.5f * (ux - gx); qBu.y = 0.5f * (uy + gy);
                qBp.x = 0.5f * (ux + gx); qBp.y = 0.5f * (gy - uy);
            }

            // ---- A task ----
            cplx qAu;
            if (u != 0) {
                float e2x = (cbA - sbA) * SQRT_HALF, e2y = (cbA + sbA) * SQRT_HALF;
                float t2x = 2.0f * e2x * e2y, t2y = 2.0f * cbA * sbA;
                float tx = t2x * t2x - t2y * t2y, ty = 2.0f * t2x * t2y;
                float s1x = xa.x * cbA + xf2.x * sbA, s1y = xa.x * sbA - xf2.x * cbA;
                float s2x = xc.x * e2x + xd2.x * e2y, s2y = xc.x * e2y - xd2.x * e2x;
                float ux = s1x + s2x, uy = s1y + s2y;
                float vx = s1x - s2x, vy = s1y - s2y;
                float gx = tx * vy + ty * vx, gy = tx * vx - ty * vy;
                qAu.x = 0.5f * (ux - gx); qAu.y = 0.5f * (uy + gy);
                int pA = 4096 - u;
                zA[pA + (pA >> 8)] = make_float2(0.5f * (ux + gx), 0.5f * (gy - uy));
            } else {
                // q_0 from (x0, x8192):
                float x0 = xa.x, x8192 = xc.x;
                float ux = 2.0f * x0 + 2.0f * SQRT_HALF * x8192;
                float vx = 2.0f * x0 - 2.0f * SQRT_HALF * x8192;
                qAu.x = 0.5f * ux; qAu.y = 0.5f * vx;
                // q_2048 (m=4096, self-partner) from (x4096, x12288):
                const float c8 = 0.92387953251128675613f;
                const float s8 = 0.38268343236508977173f;
                float p2x = x2[2048].x, p2y = x2[6144].x;
                float e2x = (c8 - s8) * SQRT_HALF, e2y = (c8 + s8) * SQRT_HALF;
                float t2x = 2.0f * e2x * e2y, t2y = 2.0f * c8 * s8;
                float tx = t2x * t2x - t2y * t2y, ty = 2.0f * t2x * t2y;
                float s1x = p2x * c8 + p2y * s8, s1y = p2x * s8 - p2y * c8;
                float s2x = p2y * e2x + p2x * e2y, s2y = p2y * e2y - p2x * e2x;
                float ux2 = s1x + s2x, uy2 = s1y + s2y;
                float vx2 = s1x - s2x, vy2 = s1y - s2y;
                float gx = tx * vy2 + ty * vx2, gy = tx * vx2 - ty * vy2;
                zA[2056] = make_float2(0.5f * (ux2 - gx), 0.5f * (uy2 + gy));  // skidx(2048)
            }

            zA[tb + 514 * n1] = make_float2(qAu.x, qAu.y);   // skidx(u) = tb + 514*n1
            zB[tb + 514 * n1] = make_float2(qBu.x, qBu.y);
            int pB = 4095 - u;
            zB[pB + (pB >> 8)] = make_float2(qBp.x, qBp.y);

            float n1c = cbA * cD - sbA * sD; sbA = sbA * cD + cbA * sD; cbA = n1c;
            float n2c = cbB * cD - sbB * sD; sbB = sbB * cD + cbB * sD; cbB = n2c;
        }
    }
    __syncthreads();

    // ---- Pass 1: radix-16 over hi digit, twiddle W_4096^{+tp*k1}.
    // Positions p = n1*256+tp -> plane index 257*n1 + tp: immediate offsets.
    {
        const int tp = t & 255;
        float2* base = ((t >> 8) ? zB : zA) + tp;
        float w1c, w1s;
        __sincosf((float)tp * (2.0f * PI_F / 4096.0f), &w1s, &w1c);
        cplx r[16];
        #pragma unroll
        for (int n1 = 0; n1 < 16; n1++) {
            float2 v = base[257 * n1];
            r[n1].x = v.x; r[n1].y = v.y;
        }
        fft16_inv(r, NEG1);
        float wc = 1.0f, ws = 0.0f;
        #pragma unroll
        for (int k1 = 0; k1 < 16; k1++) {
            const int i = REV4[k1];
            float vx = r[i].x * wc - r[i].y * ws;
            float vy = r[i].x * ws + r[i].y * wc;
            base[257 * k1] = make_float2(vx, vy);
            float nwc = wc * w1c - ws * w1s;
            ws = ws * w1c + wc * w1s;
            wc = nwc;
        }
    }
    __syncthreads();

    // ---- Pass 2: radix-16 over middle digit, twiddle W_256^{+b*k2}.
    // Positions p = k1*256 + a*16 + b -> index 257*k1 + 16*a + b.
    {
        const int th = t & 255;
        const int k1 = th & 15;
        const int b  = th >> 4;
        float2* base = ((t >> 8) ? zB : zA) + 257 * k1 + b;
        float w2c, w2s;
        __sincosf((float)b * (PI_F / 128.0f), &w2s, &w2c);
        cplx r[16];
        #pragma unroll
        for (int a = 0; a < 16; a++) {
            float2 v = base[16 * a];
            r[a].x = v.x; r[a].y = v.y;
        }
        fft16_inv(r, NEG1);
        float wc = 1.0f, ws = 0.0f;
        #pragma unroll
        for (int k2 = 0; k2 < 16; k2++) {
            const int i = REV4[k2];
            float vx = r[i].x * wc - r[i].y * ws;
            float vy = r[i].x * ws + r[i].y * wc;
            base[16 * k2] = make_float2(vx, vy);
            float nwc = wc * w2c - ws * w2s;
            ws = ws * w2c + wc * w2s;
            wc = nwc;
        }
    }
    __syncthreads();

    // ---- Pass 3: radix-16 over low digit, no twiddle.
    // Positions p = k1*256 + c*16 + d -> index 257*k1 + 16*c + d.
    {
        const int th = t & 255;
        const int k1 = th & 15;
        const int c  = th >> 4;
        float2* base = ((t >> 8) ? zB : zA) + 257 * k1 + 16 * c;
        cplx r[16];
        #pragma unroll
        for (int d = 0; d < 16; d++) {
            float2 v = base[d];
            r[d].x = v.x; r[d].y = v.y;
        }
        fft16_inv(r, NEG1);
        #pragma unroll
        for (int i = 0; i < 16; i++) {
            base[REV4[i]] = make_float2(r[i].x, r[i].y);
        }
    }
    __syncthreads();

    // ---- Gather (pair-dedup): thread emits outputs qo AND 4095-qo.
    // z_qo       = A + w^qo B            z_{4096+qo} = A - w^qo B
    // z_{8191-qo}= M + conj(w^{qo+1}) N  z_{4095-qo} = M - conj(w^{qo+1}) N
    // y4[p] = (Re z_p, Im z_{8191-p}, Im z_p, Re z_{8191-p})
    {
        float4* y4 = (float4*)(y + (size_t)row * NFFT);
        const float c1 = 0.99999970586288222663f;      // cos(2*pi/8192)
        const float s1 = 7.66990318742704526939e-4f;   // sin(2*pi/8192)
        const float cS = 0.92387953251128675613f;      // cos(pi/8)   (qo step 512)
        const float sS = 0.38268343236508977173f;      // sin(pi/8)
        float wc, ws;
        __sincosf((float)t * (2.0f * PI_F / 8192.0f), &ws, &wc);
        const int d0  = t & 15, d1 = (t >> 4) & 15, d2b = t >> 8;
        const int baseA = 257 * d0 + 16 * d1 + d2b;
        const int baseM = 257 * (15 - d0) + 16 * (15 - d1) + (15 - d2b);
        #pragma unroll
        for (int jj = 0; jj < 4; jj++) {
            int qo = t + THREADS * jj;                 // [0, 2048)
            int iA = baseA + 2 * jj;                   // skidx of z_qo position
            int iM = baseM - 2 * jj;                   // skidx of z_{4095-qo}
            float2 A  = zA[iA];
            float2 B  = zB[iA];
            float2 M  = zA[iM];
            float2 Nw = zB[iM];
            float ox = wc * c1 - ws * s1;              // w^{qo+1}
            float oy = wc * s1 + ws * c1;
            cplx wB, oN, Ac, Mc;
            wB.x = wc * B.x - ws * B.y;
            wB.y = wc * B.y + ws * B.x;
            oN.x = ox * Nw.x + oy * Nw.y;              // conj(w^{qo+1}) * N
            oN.y = ox * Nw.y - oy * Nw.x;
            Ac.x = A.x; Ac.y = A.y;
            Mc.x = M.x; Mc.y = M.y;
            cplx z1 = padd(Ac, wB);                    // z_qo
            cplx z3 = psub(Ac, wB, NEG1);              // z_{4096+qo}
            cplx z2 = padd(Mc, oN);                    // z_{8191-qo}
            cplx z4 = psub(Mc, oN, NEG1);              // z_{4095-qo}
            y4[qo]        = make_float4(z1.x, z2.y, z1.y, z2.x);
            y4[4095 - qo] = make_float4(z4.x, z3.y, z4.y, z3.x);
            float nwc = wc * cS - ws * sS;             // w *= e^{j*pi/8}
            ws = ws * cS + wc * sS;
            wc = nwc;
        }
    }
}

extern "C" void kernel_launch(void* const* d_in, const int* in_sizes, int n_in,
                              void* d_out, int out_size)
{
    const float* x = (const float*)d_in[0];
    float*       y = (float*)d_out;

    const int rows = in_sizes[0] / NFFT;
    const int smem_bytes = 2 * SKEWN * (int)sizeof(float2);   // 65792 B

    cudaFuncSetAttribute(idxct_kernel,
                         cudaFuncAttributeMaxDynamicSharedMemorySize, smem_bytes);

    idxct_kernel<<<rows, THREADS, smem_bytes>>>(x, y);
}